// round 8
// baseline (speedup 1.0000x reference)
#include <cuda_runtime.h>
#include <cuda_bf16.h>

// PatchEmbed: x (16,64,256,256) f32 -> out (16, 16384, 256) f32  + 4-float shape tail
//
// out[n][j*128 + i][c*4 + ph*2 + pw] = x[n][c][2*i + ph][2*j + pw]
//
// pw pair = one float2. Per (n,i) plane: 128x128 float2 transpose between
// J (input-contiguous) and r = c*2+ph (output-contiguous). Tiled smem
// transpose, float4-vectorized on both global sides.
//
// float2-unit strides:
//   input : n: 2097152, c: 32768, i: 256, ph: 128, j: 1
//   output: n: 2097152, j: 16384, i: 128, r: 1
//
// The ori_shape tail (harness packs the int32 reference into the float32
// d_out buffer -> write AS FLOATS) is folded into block (0,0): single graph node.

#define TILE 32

__global__ void patch_transpose_kernel(const float4* __restrict__ x,
                                       float4* __restrict__ out,
                                       float* __restrict__ tail,   // null if absent
                                       long tail_base) {
    // tile[r][j] in float2 units, +1 float2 padding per row
    __shared__ float2 tile[TILE][TILE + 1];

    const int t     = blockIdx.x;      // 0..15 : 4 j-tiles x 4 r-tiles
    const int tj    = t & 3;
    const int tr    = t >> 2;
    const int plane = blockIdx.y;      // n*128 + i
    const int n     = plane >> 7;
    const int i     = plane & 127;

    const int tx = threadIdx.x;        // 0..31
    const int ty = threadIdx.y;        // 0..7

    // ori_shape tail: one thread of one block
    if (tail && blockIdx.x == 0 && blockIdx.y == 0 && tx == 0 && ty == 0) {
        tail[tail_base + 0] = 16.0f;
        tail[tail_base + 1] = 64.0f;
        tail[tail_base + 2] = 256.0f;
        tail[tail_base + 3] = 256.0f;
    }

    // lane -> (row 0..15, half-row col pair 0..15) for float4 transactions
    const int lrow = (ty * 32 + tx) >> 4;          // 0..15
    const int lcol = tx & 15;                      // 0..15 (x2 float2s)

    // ---- Load phase: rows = r (strided), cols = j (contiguous, float4) ----
    {
        const long in_base_f4 = ((long)n * 2097152 + (long)i * 256) >> 1; // float4 units
        #pragma unroll
        for (int k = 0; k < 2; k++) {
            const int r  = tr * TILE + lrow + k * 16;  // r = c*2 + ph
            const int c  = r >> 1;
            const int ph = r & 1;
            const int j2 = tj * (TILE / 2) + lcol;     // float4 index along j
            float4 v = x[in_base_f4 + ((long)c * 32768 + ph * 128) / 2 + j2];
            tile[r - tr * TILE][lcol * 2 + 0] = make_float2(v.x, v.y);
            tile[r - tr * TILE][lcol * 2 + 1] = make_float2(v.z, v.w);
        }
    }
    __syncthreads();

    // ---- Store phase: rows = j (strided), cols = r (contiguous, float4) ----
    {
        const long out_base_f4 = ((long)n * 2097152 + (long)i * 128) >> 1; // float4 units
        #pragma unroll
        for (int k = 0; k < 2; k++) {
            const int j  = tj * TILE + lrow + k * 16;
            const int r2 = lcol;                        // float4 index along r within tile
            float2 a = tile[r2 * 2 + 0][j - tj * TILE];
            float2 b = tile[r2 * 2 + 1][j - tj * TILE];
            float4 v = make_float4(a.x, a.y, b.x, b.y);
            out[out_base_f4 + ((long)j * 16384) / 2 + tr * (TILE / 2) + r2] = v;
        }
    }
}

extern "C" void kernel_launch(void* const* d_in, const int* in_sizes, int n_in,
                              void* d_out, int out_size) {
    const float4* x = (const float4*)d_in[0];
    float4* out     = (float4*)d_out;

    const long main_elems = 16L * 16384L * 256L;  // 67108864 floats
    float* tail = ((long)out_size >= main_elems + 4) ? (float*)d_out : nullptr;

    dim3 grid(16, 2048, 1);   // 16 tiles/plane, 16*128 planes
    dim3 block(32, 8, 1);
    patch_transpose_kernel<<<grid, block>>>(x, out, tail, main_elems);
}